// round 2
// baseline (speedup 1.0000x reference)
#include <cuda_runtime.h>
#include <cuda_bf16.h>

// B=16, N_VEC=2048, N_DIM=32, N_W=4, N_HID=128, VOCAB=32000, N_CLASS=10

typedef unsigned long long u64;

__device__ __forceinline__ u64 fma2(u64 a, u64 b, u64 c) {
    u64 d;
    asm("fma.rn.f32x2 %0, %1, %2, %3;" : "=l"(d) : "l"(a), "l"(b), "l"(c));
    return d;
}
__device__ __forceinline__ u64 pack2(float lo, float hi) {
    u64 r;
    asm("mov.b64 %0, {%1, %2};" : "=l"(r) : "f"(lo), "f"(hi));
    return r;
}
__device__ __forceinline__ float2 unpack2(u64 v) {
    float2 f;
    asm("mov.b64 {%0, %1}, %2;" : "=f"(f.x), "=f"(f.y) : "l"(v));
    return f;
}

// ---------- scratch (device globals; allocation is forbidden) ----------
__device__ float g_X [16 * 2048 * 32];
__device__ float g_VA[16 * 2048 * 32];
__device__ float g_VB[16 * 2048 * 32];
__device__ float g_Upart[16 * 16 * 129 * 32];   // [b][chunk][129][32] (row 128 = bias c)
__device__ float g_U[16 * 129 * 32];            // [b][129][32]
__device__ float g_partF[16 * 32 * 10];
__device__ int   g_is64;

// ---------- int64 vs int32 detection on `data` ----------
__global__ void k_detect(const int* __restrict__ d32) {
    __shared__ int nz;
    if (threadIdx.x == 0) nz = 0;
    __syncthreads();
    if (d32[2 * threadIdx.x + 1] != 0) nz = 1;   // hi words of int64 are all 0 (vals < 32000)
    __syncthreads();
    if (threadIdx.x == 0) g_is64 = (nz == 0) ? 1 : 0;
}

// ---------- X = emb[data] ----------
__global__ __launch_bounds__(256) void k_gather(const int* __restrict__ d32,
                                                const float* __restrict__ emb) {
    int t = blockIdx.x * 256 + threadIdx.x;      // over 16*2048*8 float4s
    int row = t >> 3, q = t & 7;
    int idx = g_is64 ? d32[row * 2] : d32[row];
    float4 v = *reinterpret_cast<const float4*>(emb + (size_t)idx * 32 + q * 4);
    *reinterpret_cast<float4*>(g_X + (size_t)row * 32 + q * 4) = v;
}

// ---------- U partials: U[b] = fw2[layer] @ V[b], c[b] = fb2[layer] . V[b] ----------
// grid (16 K-chunks, 16 batch), 256 threads; thread tile 4h x 4d, f32x2 along K(=m).
__global__ __launch_bounds__(256) void k_upart(const float* __restrict__ fw2,
                                               const float* __restrict__ fb2,
                                               int vin_sel, int layer) {
    __shared__ float VsT[32 * 130];              // [d][m], pad 130
    int b = blockIdx.y, ch = blockIdx.x, tid = threadIdx.x;
    int m0 = ch * 128;
    const float* Vin = (vin_sel == 0) ? g_X : (vin_sel == 1 ? g_VA : g_VB);
    const float* vg = Vin + ((size_t)(b * 2048 + m0)) * 32;
#pragma unroll
    for (int it = 0; it < 16; ++it) {
        int t = tid + it * 256;                  // t = m*32 + d
        VsT[(t & 31) * 130 + (t >> 5)] = vg[t];
    }
    __syncthreads();

    int dt = tid & 7, ht = tid >> 3;
    int d0 = dt * 4, h0 = ht * 4;
    const float* w0 = fw2 + ((size_t)(layer * 128 + h0)) * 2048 + m0;

    u64 acc[4][4];
#pragma unroll
    for (int a = 0; a < 4; ++a)
#pragma unroll
        for (int c = 0; c < 4; ++c) acc[a][c] = 0ull;

#pragma unroll 4
    for (int m = 0; m < 64; ++m) {               // 2 K-elems per iter
        u64 va[4];
#pragma unroll
        for (int kd = 0; kd < 4; ++kd)
            va[kd] = *reinterpret_cast<const u64*>(VsT + (d0 + kd) * 130 + 2 * m);
#pragma unroll
        for (int kh = 0; kh < 4; ++kh) {
            u64 w = *reinterpret_cast<const u64*>(w0 + (size_t)kh * 2048 + 2 * m);
#pragma unroll
            for (int kd = 0; kd < 4; ++kd) acc[kh][kd] = fma2(w, va[kd], acc[kh][kd]);
        }
    }

    float* up = g_Upart + (((size_t)(b * 16 + ch)) * 129 + h0) * 32 + d0;
#pragma unroll
    for (int kh = 0; kh < 4; ++kh) {
        float2 s0 = unpack2(acc[kh][0]), s1 = unpack2(acc[kh][1]);
        float2 s2 = unpack2(acc[kh][2]), s3 = unpack2(acc[kh][3]);
        *reinterpret_cast<float4*>(up + (size_t)kh * 32) =
            make_float4(s0.x + s0.y, s1.x + s1.y, s2.x + s2.y, s3.x + s3.y);
    }

    if (tid < 8) {                               // bias row c (h == 128)
        int db = tid * 4;
        const float* wb = fb2 + (size_t)layer * 2048 + m0;
        u64 a[4] = {0ull, 0ull, 0ull, 0ull};
        for (int m = 0; m < 64; ++m) {
            u64 w2 = *reinterpret_cast<const u64*>(wb + 2 * m);
#pragma unroll
            for (int k = 0; k < 4; ++k)
                a[k] = fma2(w2, *reinterpret_cast<const u64*>(VsT + (db + k) * 130 + 2 * m), a[k]);
        }
        float2 s0 = unpack2(a[0]), s1 = unpack2(a[1]), s2 = unpack2(a[2]), s3 = unpack2(a[3]);
        *reinterpret_cast<float4*>(g_Upart + (((size_t)(b * 16 + ch)) * 129 + 128) * 32 + db) =
            make_float4(s0.x + s0.y, s1.x + s1.y, s2.x + s2.y, s3.x + s3.y);
    }
}

// ---------- reduce split-K partials ----------
__global__ __launch_bounds__(256) void k_ured() {
    int idx = blockIdx.x * 256 + threadIdx.x;    // 66048 = 258*256 exactly
    int b = idx / 4128, r = idx - b * 4128;
    float s = 0.f;
#pragma unroll
    for (int c = 0; c < 16; ++c) s += g_Upart[((size_t)(b * 16 + c)) * 4128 + r];
    g_U[(size_t)b * 4128 + r] = s;
}

// ---------- fused: H = gelu(X @ fw1 + fb1); V' = H @ U + c ----------
// grid (64 row-tiles, 16 batch), 128 threads, 32 rows/block. H never hits HBM.
__global__ __launch_bounds__(128) void k_vupd(const float* __restrict__ fw1,
                                              const float* __restrict__ fb1,
                                              int vout_sel, int layer) {
    __shared__ float Xs[32 * 32];                // [r][d]
    __shared__ float Us[129 * 32];               // [j][d]
    __shared__ float Hs[32 * 132];               // [r][j], pad 132
    int b = blockIdx.y, n0 = blockIdx.x * 32, tid = threadIdx.x;

    const float* xg = g_X + ((size_t)(b * 2048 + n0)) * 32;
#pragma unroll
    for (int it = 0; it < 8; ++it) Xs[tid + it * 128] = xg[tid + it * 128];
    const float* Ug = g_U + (size_t)b * 4128;
    for (int t = tid; t < 4128; t += 128) Us[t] = Ug[t];
    __syncthreads();

    // phase 1: thread j computes H[r][j] for all 32 rows (f32x2 along d)
    {
        int j = tid;
        const float* w = fw1 + (size_t)layer * 4096 + j;   // column j, stride 128
        u64 wcol[16];
#pragma unroll
        for (int t = 0; t < 16; ++t) wcol[t] = pack2(w[(2 * t) * 128], w[(2 * t + 1) * 128]);
        float bj = fb1[layer * 128 + j];
#pragma unroll 4
        for (int r = 0; r < 32; ++r) {
            const u64* xq = reinterpret_cast<const u64*>(Xs + r * 32);
            u64 a = 0ull;
#pragma unroll
            for (int t = 0; t < 16; ++t) a = fma2(xq[t], wcol[t], a);
            float2 s = unpack2(a);
            float x = s.x + s.y + bj;
            Hs[r * 132 + j] = 0.5f * x * (1.0f + erff(x * 0.70710678118654752f));
        }
    }
    __syncthreads();

    // phase 2: thread handles 2 rows x 4 cols; f32x2 along d
    {
        int rp = tid >> 3, dg = tid & 7;
        int r0 = rp * 2, d0 = dg * 4;
        u64 acc[2][2] = {{0ull, 0ull}, {0ull, 0ull}};
#pragma unroll 4
        for (int j = 0; j < 128; ++j) {
            u64 u0 = *reinterpret_cast<const u64*>(Us + j * 32 + d0);
            u64 u1 = *reinterpret_cast<const u64*>(Us + j * 32 + d0 + 2);
            float h0 = Hs[r0 * 132 + j], h1 = Hs[(r0 + 1) * 132 + j];
            u64 h0p = pack2(h0, h0), h1p = pack2(h1, h1);
            acc[0][0] = fma2(h0p, u0, acc[0][0]);
            acc[0][1] = fma2(h0p, u1, acc[0][1]);
            acc[1][0] = fma2(h1p, u0, acc[1][0]);
            acc[1][1] = fma2(h1p, u1, acc[1][1]);
        }
        float* Vout = (vout_sel == 1) ? g_VA : g_VB;
        const float* crow = Us + 128 * 32 + d0;
        float c0 = crow[0], c1 = crow[1], c2 = crow[2], c3 = crow[3];
#pragma unroll
        for (int rr = 0; rr < 2; ++rr) {
            float2 p0 = unpack2(acc[rr][0]), p1 = unpack2(acc[rr][1]);
            *reinterpret_cast<float4*>(Vout + ((size_t)(b * 2048 + n0 + r0 + rr)) * 32 + d0) =
                make_float4(p0.x + c0, p0.y + c1, p1.x + c2, p1.y + c3);
        }
    }
}

// ---------- final projection partials: out = V.reshape(16,65536) @ Wf + bf ----------
__global__ __launch_bounds__(256) void k_fpart(const float* __restrict__ Wf) {
    __shared__ float red[256];
    int b = blockIdx.y, ch = blockIdx.x, tid = threadIdx.x;
    int k0 = ch * 2048;
    float acc[10];
#pragma unroll
    for (int c = 0; c < 10; ++c) acc[c] = 0.f;
#pragma unroll
    for (int q = 0; q < 8; ++q) {
        int k = k0 + q * 256 + tid;
        float v = g_VB[(size_t)b * 65536 + k];
        const float* wr = Wf + (size_t)k * 10;
#pragma unroll
        for (int c = 0; c < 10; ++c) acc[c] += v * wr[c];
    }
#pragma unroll
    for (int c = 0; c < 10; ++c) {
        red[tid] = acc[c];
        __syncthreads();
#pragma unroll
        for (int s = 128; s > 0; s >>= 1) {
            if (tid < s) red[tid] += red[tid + s];
            __syncthreads();
        }
        if (tid == 0) g_partF[((size_t)(b * 32 + ch)) * 10 + c] = red[0];
        __syncthreads();
    }
}

__global__ void k_ffin(const float* __restrict__ bf, float* __restrict__ out) {
    int t = threadIdx.x;
    if (t >= 160) return;
    int b = t / 10, c = t % 10;
    float s = bf[c];
#pragma unroll
    for (int ch = 0; ch < 32; ++ch) s += g_partF[((size_t)(b * 32 + ch)) * 10 + c];
    out[t] = s;
}

extern "C" void kernel_launch(void* const* d_in, const int* in_sizes, int n_in,
                              void* d_out, int out_size) {
    const int*   data = (const int*)  d_in[0];
    const float* emb  = (const float*)d_in[1];
    const float* fw1  = (const float*)d_in[2];
    const float* fb1  = (const float*)d_in[3];
    const float* fw2  = (const float*)d_in[4];
    const float* fb2  = (const float*)d_in[5];
    const float* Wf   = (const float*)d_in[6];
    const float* bf   = (const float*)d_in[7];
    float* out = (float*)d_out;

    k_detect<<<1, 256>>>(data);
    k_gather<<<1024, 256>>>(data, emb);

    // layers i = 3,2,1,0 ; V ping-pong: X -> VA -> VB -> VA -> VB
    int vin = 0;
    for (int it = 0; it < 4; ++it) {
        int layer = 3 - it;
        int vout = (vin == 1) ? 2 : 1;
        k_upart<<<dim3(16, 16), 256>>>(fw2, fb2, vin, layer);
        k_ured<<<258, 256>>>();
        k_vupd<<<dim3(64, 16), 128>>>(fw1, fb1, vout, layer);
        vin = vout;
    }

    k_fpart<<<dim3(32, 16), 256>>>(Wf);
    k_ffin<<<1, 192>>>(bf, out);
}

// round 3
// speedup vs baseline: 1.1340x; 1.1340x over previous
#include <cuda_runtime.h>
#include <cuda_bf16.h>

// B=16, N_VEC=2048, N_DIM=32, N_W=4, N_HID=128, VOCAB=32000, N_CLASS=10

typedef unsigned long long u64;

__device__ __forceinline__ u64 fma2(u64 a, u64 b, u64 c) {
    u64 d;
    asm("fma.rn.f32x2 %0, %1, %2, %3;" : "=l"(d) : "l"(a), "l"(b), "l"(c));
    return d;
}
__device__ __forceinline__ u64 pack2(float lo, float hi) {
    u64 r;
    asm("mov.b64 %0, {%1, %2};" : "=l"(r) : "f"(lo), "f"(hi));
    return r;
}
__device__ __forceinline__ float2 unpack2(u64 v) {
    float2 f;
    asm("mov.b64 {%0, %1}, %2;" : "=f"(f.x), "=f"(f.y) : "l"(v));
    return f;
}

// ---------- scratch (device globals; allocation is forbidden) ----------
__device__ float g_X [16 * 2048 * 32];
__device__ float g_VA[16 * 2048 * 32];
__device__ float g_VB[16 * 2048 * 32];
__device__ float g_Upart[16 * 16 * 129 * 32];   // [b][chunk][129][32] (row 128 = bias c)
__device__ float g_U[16 * 129 * 32];            // [b][129][32]
__device__ float g_partF[16 * 32 * 10];
__device__ unsigned g_tick;

// ---------- X = emb[data], with per-block int64/int32 detection ----------
__global__ __launch_bounds__(256) void k_gather(const int* __restrict__ d32,
                                                const float* __restrict__ emb) {
    __shared__ int s_is64;
    int tid = threadIdx.x;
    if (tid == 0) s_is64 = 1;
    __syncthreads();
    // If data is int64 (LE, values < 32000) every odd 32-bit word is 0.
    // Words 1,3,..,63 are in-bounds for both layouts. P(all 0 | int32) ~ 0.
    if (tid < 32) { if (d32[2 * tid + 1] != 0) s_is64 = 0; }
    __syncthreads();
    int t = blockIdx.x * 256 + tid;              // over 16*2048*8 float4s
    int row = t >> 3, q = t & 7;
    int idx = s_is64 ? d32[row * 2] : d32[row];
    float4 v = *reinterpret_cast<const float4*>(emb + (size_t)idx * 32 + q * 4);
    *reinterpret_cast<float4*>(g_X + (size_t)row * 32 + q * 4) = v;
}

// ---------- U partials: U[b] = fw2[layer] @ V[b], c[b] = fb2[layer] . V[b] ----------
// grid (16 K-chunks, 16 batch), 256 threads; thread tile 4h x 4d, f32x2 along K(=m).
__global__ __launch_bounds__(256) void k_upart(const float* __restrict__ fw2,
                                               const float* __restrict__ fb2,
                                               int vin_sel, int layer) {
    __shared__ __align__(16) float VsT[32 * 130];   // [d][m], pad 130
    int b = blockIdx.y, ch = blockIdx.x, tid = threadIdx.x;
    int m0 = ch * 128;
    const float* Vin = (vin_sel == 0) ? g_X : (vin_sel == 1 ? g_VA : g_VB);
    const float* vg = Vin + ((size_t)(b * 2048 + m0)) * 32;
#pragma unroll
    for (int it = 0; it < 16; ++it) {
        int t = tid + it * 256;                  // t = m*32 + d
        VsT[(t & 31) * 130 + (t >> 5)] = vg[t];
    }
    __syncthreads();

    int dt = tid & 7, ht = tid >> 3;
    int d0 = dt * 4, h0 = ht * 4;
    const float* w0 = fw2 + ((size_t)(layer * 128 + h0)) * 2048 + m0;

    u64 acc[4][4];
#pragma unroll
    for (int a = 0; a < 4; ++a)
#pragma unroll
        for (int c = 0; c < 4; ++c) acc[a][c] = 0ull;

#pragma unroll 4
    for (int m = 0; m < 64; ++m) {               // 2 K-elems per iter
        u64 va[4];
#pragma unroll
        for (int kd = 0; kd < 4; ++kd)
            va[kd] = *reinterpret_cast<const u64*>(VsT + (d0 + kd) * 130 + 2 * m);
#pragma unroll
        for (int kh = 0; kh < 4; ++kh) {
            u64 w = *reinterpret_cast<const u64*>(w0 + (size_t)kh * 2048 + 2 * m);
#pragma unroll
            for (int kd = 0; kd < 4; ++kd) acc[kh][kd] = fma2(w, va[kd], acc[kh][kd]);
        }
    }

    float* up = g_Upart + (((size_t)(b * 16 + ch)) * 129 + h0) * 32 + d0;
#pragma unroll
    for (int kh = 0; kh < 4; ++kh) {
        float2 s0 = unpack2(acc[kh][0]), s1 = unpack2(acc[kh][1]);
        float2 s2 = unpack2(acc[kh][2]), s3 = unpack2(acc[kh][3]);
        *reinterpret_cast<float4*>(up + (size_t)kh * 32) =
            make_float4(s0.x + s0.y, s1.x + s1.y, s2.x + s2.y, s3.x + s3.y);
    }

    if (tid < 8) {                               // bias row c (h == 128)
        int db = tid * 4;
        const float* wb = fb2 + (size_t)layer * 2048 + m0;
        u64 a[4] = {0ull, 0ull, 0ull, 0ull};
        for (int m = 0; m < 64; ++m) {
            u64 w2 = *reinterpret_cast<const u64*>(wb + 2 * m);
#pragma unroll
            for (int k = 0; k < 4; ++k)
                a[k] = fma2(w2, *reinterpret_cast<const u64*>(VsT + (db + k) * 130 + 2 * m), a[k]);
        }
        float2 s0 = unpack2(a[0]), s1 = unpack2(a[1]), s2 = unpack2(a[2]), s3 = unpack2(a[3]);
        *reinterpret_cast<float4*>(g_Upart + (((size_t)(b * 16 + ch)) * 129 + 128) * 32 + db) =
            make_float4(s0.x + s0.y, s1.x + s1.y, s2.x + s2.y, s3.x + s3.y);
    }
}

// ---------- reduce split-K partials (vectorized, MLP=16) ----------
__global__ __launch_bounds__(256) void k_ured() {
    int idx = blockIdx.x * 256 + threadIdx.x;    // over 16*1032 float4s
    if (idx >= 16 * 1032) return;
    int b = idx / 1032, r4 = idx - b * 1032;
    const float4* base = reinterpret_cast<const float4*>(g_Upart) + (size_t)b * 16 * 1032 + r4;
    float4 s = make_float4(0.f, 0.f, 0.f, 0.f);
#pragma unroll
    for (int c = 0; c < 16; ++c) {
        float4 v = base[(size_t)c * 1032];
        s.x += v.x; s.y += v.y; s.z += v.z; s.w += v.w;
    }
    reinterpret_cast<float4*>(g_U)[(size_t)b * 1032 + r4] = s;
}

// ---------- fused: H = gelu(X @ fw1 + fb1); V' = H @ U + c ----------
// grid (64 row-tiles, 16 batch), 128 threads, 32 rows/block. H stays in smem (transposed).
__global__ __launch_bounds__(128) void k_vupd(const float* __restrict__ fw1,
                                              const float* __restrict__ fb1,
                                              int vout_sel, int layer) {
    __shared__ __align__(16) float Xs[32 * 32];     // [r][d]
    __shared__ __align__(16) float Us[129 * 32];    // [j][d]
    __shared__ __align__(16) float HsT[128 * 34];   // [j][r], pad 34 (keeps 8B align)
    int b = blockIdx.y, n0 = blockIdx.x * 32, tid = threadIdx.x;

    const float* xg = g_X + ((size_t)(b * 2048 + n0)) * 32;
#pragma unroll
    for (int it = 0; it < 8; ++it) Xs[tid + it * 128] = xg[tid + it * 128];
    const float* Ug = g_U + (size_t)b * 4128;
#pragma unroll
    for (int it = 0; it < 32; ++it) Us[tid + it * 128] = Ug[tid + it * 128];
    if (tid < 32) Us[4096 + tid] = Ug[4096 + tid];
    __syncthreads();

    // phase 1: thread handles 2 adjacent columns (jA, jB) x 16 rows; f32x2 along d.
    {
        int jA = (tid & 63) * 2, jB = jA + 1;
        int half = tid >> 6;
        const float* wbase = fw1 + (size_t)layer * 4096;
        u64 wcA[16], wcB[16];
#pragma unroll
        for (int k = 0; k < 16; ++k) {
            float2 r0 = *reinterpret_cast<const float2*>(wbase + (2 * k) * 128 + jA);
            float2 r1 = *reinterpret_cast<const float2*>(wbase + (2 * k + 1) * 128 + jA);
            wcA[k] = pack2(r0.x, r1.x);
            wcB[k] = pack2(r0.y, r1.y);
        }
        float bjA = fb1[layer * 128 + jA], bjB = fb1[layer * 128 + jB];
        int rbase = half * 16;
#pragma unroll 2
        for (int rr = 0; rr < 16; ++rr) {
            int r = rbase + rr;
            const u64* xq = reinterpret_cast<const u64*>(Xs + r * 32);
            u64 aA = 0ull, aB = 0ull;
#pragma unroll
            for (int k = 0; k < 16; ++k) {
                u64 x = xq[k];
                aA = fma2(x, wcA[k], aA);
                aB = fma2(x, wcB[k], aB);
            }
            float2 sA = unpack2(aA), sB = unpack2(aB);
            float xA = sA.x + sA.y + bjA;
            float xB = sB.x + sB.y + bjB;
            HsT[jA * 34 + r] = 0.5f * xA * (1.0f + erff(xA * 0.70710678118654752f));
            HsT[jB * 34 + r] = 0.5f * xB * (1.0f + erff(xB * 0.70710678118654752f));
        }
    }
    __syncthreads();

    // phase 2: thread tile 2 rows x 4 cols; per j: LDS.64(H) + LDS.128(U) + 4 FFMA2.
    {
        int rt = tid >> 3, dt = tid & 7;
        int r0 = rt * 2, d0 = dt * 4;
        u64 a00 = 0ull, a01 = 0ull, a10 = 0ull, a11 = 0ull;
#pragma unroll 4
        for (int j = 0; j < 128; ++j) {
            float2 h2 = *reinterpret_cast<const float2*>(HsT + j * 34 + r0);
            ulonglong2 u = *reinterpret_cast<const ulonglong2*>(Us + j * 32 + d0);
            u64 h0 = pack2(h2.x, h2.x), h1 = pack2(h2.y, h2.y);
            a00 = fma2(h0, u.x, a00);
            a01 = fma2(h0, u.y, a01);
            a10 = fma2(h1, u.x, a10);
            a11 = fma2(h1, u.y, a11);
        }
        float* Vout = (vout_sel == 1) ? g_VA : g_VB;
        float4 c4 = *reinterpret_cast<const float4*>(Us + 128 * 32 + d0);
        float2 p00 = unpack2(a00), p01 = unpack2(a01);
        float2 p10 = unpack2(a10), p11 = unpack2(a11);
        *reinterpret_cast<float4*>(Vout + ((size_t)(b * 2048 + n0 + r0)) * 32 + d0) =
            make_float4(p00.x + c4.x, p00.y + c4.y, p01.x + c4.z, p01.y + c4.w);
        *reinterpret_cast<float4*>(Vout + ((size_t)(b * 2048 + n0 + r0 + 1)) * 32 + d0) =
            make_float4(p10.x + c4.x, p10.y + c4.y, p11.x + c4.z, p11.y + c4.w);
    }
}

// ---------- final projection, fused partial + completion (ticket) ----------
__global__ __launch_bounds__(256) void k_fproj(const float* __restrict__ Wf,
                                               const float* __restrict__ bf,
                                               float* __restrict__ out) {
    __shared__ float wsum[8][10];
    __shared__ int s_last;
    int b = blockIdx.y, ch = blockIdx.x, tid = threadIdx.x;
    int lane = tid & 31, w = tid >> 5;
    float acc[10];
#pragma unroll
    for (int c = 0; c < 10; ++c) acc[c] = 0.f;
    const float* Vb = g_VB + (size_t)b * 65536 + ch * 2048;
#pragma unroll
    for (int q = 0; q < 8; ++q) {
        int k = q * 256 + tid;
        float v = Vb[k];
        const float* wr = Wf + (size_t)(ch * 2048 + k) * 10;
#pragma unroll
        for (int c = 0; c < 10; ++c) acc[c] += v * wr[c];
    }
#pragma unroll
    for (int c = 0; c < 10; ++c) {
#pragma unroll
        for (int s = 16; s > 0; s >>= 1) acc[c] += __shfl_down_sync(0xffffffffu, acc[c], s);
        if (lane == 0) wsum[w][c] = acc[c];
    }
    __syncthreads();
    if (tid < 10) {
        float s = 0.f;
#pragma unroll
        for (int ww = 0; ww < 8; ++ww) s += wsum[ww][tid];
        g_partF[((size_t)(b * 32 + ch)) * 10 + tid] = s;
    }
    __threadfence();
    __syncthreads();
    if (tid == 0) {
        unsigned prev = atomicAdd(&g_tick, 1u);
        s_last = (prev == 511u) ? 1 : 0;
    }
    __syncthreads();
    if (s_last) {
        __threadfence();
        if (tid < 160) {
            int bb = tid / 10, c = tid % 10;
            float s = bf[c];
#pragma unroll
            for (int cc = 0; cc < 32; ++cc) s += g_partF[((size_t)(bb * 32 + cc)) * 10 + c];
            out[tid] = s;
        }
        if (tid == 0) g_tick = 0u;   // reset for next graph replay
    }
}

extern "C" void kernel_launch(void* const* d_in, const int* in_sizes, int n_in,
                              void* d_out, int out_size) {
    const int*   data = (const int*)  d_in[0];
    const float* emb  = (const float*)d_in[1];
    const float* fw1  = (const float*)d_in[2];
    const float* fb1  = (const float*)d_in[3];
    const float* fw2  = (const float*)d_in[4];
    const float* fb2  = (const float*)d_in[5];
    const float* Wf   = (const float*)d_in[6];
    const float* bf   = (const float*)d_in[7];
    float* out = (float*)d_out;

    k_gather<<<1024, 256>>>(data, emb);

    // layers i = 3,2,1,0 ; V ping-pong: X -> VA -> VB -> VA -> VB
    int vin = 0;
    for (int it = 0; it < 4; ++it) {
        int layer = 3 - it;
        int vout = (vin == 1) ? 2 : 1;
        k_upart<<<dim3(16, 16), 256>>>(fw2, fb2, vin, layer);
        k_ured<<<65, 256>>>();
        k_vupd<<<dim3(64, 16), 128>>>(fw1, fb1, vout, layer);
        vin = vout;
    }

    k_fproj<<<dim3(32, 16), 256>>>(Wf, bf, out);
}